// round 14
// baseline (speedup 1.0000x reference)
#include <cuda_runtime.h>
#include <cuda_fp16.h>
#include <mma.h>
#include <cstdint>

using namespace nvcuda;

#define DIM 128
#define N_K_MAX 10000
#define N_E_MAX 100000
#define E_MAX   2000000
#define SCAN_CHUNK 1024
#define BK 32
#define STH 40    // stage-buffer row stride (halfs)
#define T_ST 136  // smem tile row stride (halfs)

// ---------------- scratch (static device globals; no allocation) ----------------
__device__ __half g_eh[N_E_MAX * DIM];
__device__ __half g_ii2[N_K_MAX * DIM];
__device__ __half g_iih[N_K_MAX * DIM];
__device__ __half g_keh[N_K_MAX * DIM];
__device__ __half g_n1[N_E_MAX * DIM];
__device__ __half g_t0[N_E_MAX * DIM];
__device__ __half g_srcc[N_E_MAX * DIM];
// half weights
__device__ __half g_w4h[DIM * 2 * DIM];
__device__ __half g_w1h[DIM * 2 * DIM];
__device__ __half g_ekSh[DIM * DIM], g_ekNh[DIM * DIM];
__device__ __half g_eeSh[DIM * DIM], g_eeNh[DIM * DIM];
__device__ __half g_G1[DIM * DIM], g_G2[DIM * DIM];
__device__ __half g_X1[DIM * DIM], g_X2[DIM * DIM];
__device__ __half g_F1[DIM * DIM], g_F2[DIM * DIM];
// fp32 fold intermediates + biases
__device__ float g_M2s[DIM * DIM], g_M2n[DIM * DIM], g_P[DIM * DIM];
__device__ float g_b2[DIM], g_bf[DIM], g_gb[DIM], g_bout[DIM];
// belong CSR
__device__ int   g_cntB[N_E_MAX];
__device__ int   g_rowB[N_E_MAX];
__device__ int   g_curB[N_E_MAX];
__device__ int   g_choffB[256];
__device__ int   g_esrcB[E_MAX];
// collab CSR (packed src+ew)
__device__ int   g_cntC[N_E_MAX];
__device__ int   g_rowC[N_E_MAX];
__device__ int   g_curC[N_E_MAX];
__device__ int   g_choffC[256];
__device__ int2  g_epkC[E_MAX];

// ---------------- float -> half conversion ----------------
__global__ void k_f2h(__half* __restrict__ dst, const float* __restrict__ src, int n4) {
    int i = blockIdx.x * blockDim.x + threadIdx.x;
    if (i >= n4) return;
    float4 v = ((const float4*)src)[i];
    __half2 h0 = __floats2half2_rn(v.x, v.y);
    __half2 h1 = __floats2half2_rn(v.z, v.w);
    uint2 u;
    u.x = *(uint32_t*)&h0;
    u.y = *(uint32_t*)&h1;
    ((uint2*)dst)[i] = u;
}

// ---------------- CSR build ----------------
__global__ void k_hist(const int* __restrict__ didx, int* __restrict__ cnt, int E) {
    int i = blockIdx.x * blockDim.x + threadIdx.x;
    if (i < E) atomicAdd(cnt + __ldg(didx + i), 1);
}

__global__ void k_scan1(const int* __restrict__ cnt, int* __restrict__ excl,
                        int* __restrict__ sums, int n) {
    __shared__ int warp_sums[8];
    int t = threadIdx.x;
    int lane = t & 31, w = t >> 5;
    int idx = blockIdx.x * SCAN_CHUNK + t * 4;
    int a0 = 0, a1 = 0, a2 = 0, a3 = 0;
    if (idx + 3 < n) {
        int4 v = *(const int4*)(cnt + idx);
        a0 = v.x; a1 = v.y; a2 = v.z; a3 = v.w;
    } else {
        if (idx + 0 < n) a0 = cnt[idx + 0];
        if (idx + 1 < n) a1 = cnt[idx + 1];
        if (idx + 2 < n) a2 = cnt[idx + 2];
        if (idx + 3 < n) a3 = cnt[idx + 3];
    }
    int s0 = a0, s1 = s0 + a1, s2 = s1 + a2, s3 = s2 + a3;
    int tot = s3;
    int x = tot;
    #pragma unroll
    for (int o = 1; o < 32; o <<= 1) {
        int y = __shfl_up_sync(0xffffffffu, x, o);
        if (lane >= o) x += y;
    }
    if (lane == 31) warp_sums[w] = x;
    __syncthreads();
    if (w == 0) {
        int y = (lane < 8) ? warp_sums[lane] : 0;
        #pragma unroll
        for (int o = 1; o < 8; o <<= 1) {
            int z = __shfl_up_sync(0xffffffffu, y, o);
            if (lane >= o) y += z;
        }
        if (lane < 8) warp_sums[lane] = y;
    }
    __syncthreads();
    int base = ((w > 0) ? warp_sums[w - 1] : 0) + (x - tot);
    if (idx + 0 < n) excl[idx + 0] = base;
    if (idx + 1 < n) excl[idx + 1] = base + s0;
    if (idx + 2 < n) excl[idx + 2] = base + s1;
    if (idx + 3 < n) excl[idx + 3] = base + s2;
    if (t == 0) sums[blockIdx.x] = warp_sums[7];
}

__global__ void k_scan2(const int* __restrict__ sums, int* __restrict__ off, int nchunks) {
    __shared__ int sh[256];
    int t = threadIdx.x;
    sh[t] = (t < nchunks) ? sums[t] : 0;
    __syncthreads();
    for (int o = 1; o < 256; o <<= 1) {
        int v = (t >= o) ? sh[t - o] : 0;
        __syncthreads();
        sh[t] += v;
        __syncthreads();
    }
    if (t < nchunks) off[t] = (t == 0) ? 0 : sh[t - 1];
}

__global__ void k_scan3(int* __restrict__ excl, int* __restrict__ cursor,
                        const int* __restrict__ off, int n) {
    int i = blockIdx.x * blockDim.x + threadIdx.x;
    if (i >= n) return;
    int v = excl[i] + off[i / SCAN_CHUNK];
    excl[i] = v;
    cursor[i] = v;
}

__global__ void k_scatter(const int* __restrict__ sidx, const int* __restrict__ didx,
                          int* __restrict__ cursor, int* __restrict__ esrc, int E) {
    int i = blockIdx.x * blockDim.x + threadIdx.x;
    if (i >= E) return;
    int d = __ldg(didx + i);
    int pos = atomicAdd(cursor + d, 1);
    esrc[pos] = __ldg(sidx + i);
}

__global__ void k_scatter_p(const int* __restrict__ sidx, const int* __restrict__ didx,
                            const float* __restrict__ ew, int* __restrict__ cursor,
                            int2* __restrict__ epk, int E) {
    int i = blockIdx.x * blockDim.x + threadIdx.x;
    if (i >= E) return;
    int d = __ldg(didx + i);
    int pos = atomicAdd(cursor + d, 1);
    epk[pos] = make_int2(__ldg(sidx + i), __float_as_int(__ldg(ew + i)));
}

// ---------------- weight folding (exact fp32 fold; half outputs for GEMM weights) ----------------
__global__ void k_combo1(const float* __restrict__ w2, const float* __restrict__ w2b,
                         const float* __restrict__ ekS, const float* __restrict__ ekN,
                         const float* __restrict__ ekb,
                         const float* __restrict__ combW, const float* __restrict__ w3,
                         float* __restrict__ M2s, float* __restrict__ M2n,
                         float* __restrict__ b2, float* __restrict__ P)
{
    int j = blockIdx.x, k = threadIdx.x;
    const float* ekS1 = ekS + DIM * DIM;
    const float* ekN1 = ekN + DIM * DIM;
    const float* ekb1 = ekb + DIM;
    float s1 = 0.f, s2 = 0.f, s3 = 0.f;
    for (int t = 0; t < DIM; t++) {
        float a = w2[j * DIM + t];
        s1 += a * ekS1[t * DIM + k];
        s2 += a * ekN1[t * DIM + k];
        float cbv = combW[j * 2 * DIM + DIM + t];
        s3 += cbv * w3[t * DIM + k];
    }
    M2s[j * DIM + k] = s1;
    M2n[j * DIM + k] = s2;
    P[j * DIM + k] = s3;
    if (k == 0) {
        float b = 0.f;
        for (int t = 0; t < DIM; t++) b += w2[j * DIM + t] * ekb1[t];
        b2[j] = b + w2b[j];
    }
}

__global__ void k_combo2(const float* __restrict__ P,
                         const float* __restrict__ eeS, const float* __restrict__ eeN,
                         const float* __restrict__ eeb,
                         const float* __restrict__ combW, const float* __restrict__ w3b,
                         const float* __restrict__ combb,
                         __half* __restrict__ F1, __half* __restrict__ F2,
                         float* __restrict__ bf)
{
    int j = blockIdx.x, k = threadIdx.x;
    const float* eeS1 = eeS + DIM * DIM;
    const float* eeN1 = eeN + DIM * DIM;
    const float* eeb1 = eeb + DIM;
    float s1 = 0.f, s2 = 0.f;
    for (int t = 0; t < DIM; t++) {
        float p = P[j * DIM + t];
        s1 += p * eeS1[t * DIM + k];
        s2 += p * eeN1[t * DIM + k];
    }
    F1[j * DIM + k] = __float2half_rn(s1);
    F2[j * DIM + k] = __float2half_rn(s2);
    if (k == 0) {
        float b = 0.f;
        for (int t = 0; t < DIM; t++)
            b += P[j * DIM + t] * eeb1[t] + combW[j * 2 * DIM + DIM + t] * w3b[t];
        bf[j] = b + combb[j];
    }
}

__global__ void k_combo3(const float* __restrict__ w1W, const float* __restrict__ w1b,
                         const float* __restrict__ combW,
                         const float* __restrict__ M2s, const float* __restrict__ M2n,
                         const float* __restrict__ b2, const float* __restrict__ bf,
                         __half* __restrict__ G1, __half* __restrict__ G2,
                         __half* __restrict__ X1, __half* __restrict__ X2,
                         float* __restrict__ gb, float* __restrict__ bout)
{
    int j = blockIdx.x, k = threadIdx.x;
    float s1 = 0.f, s2 = 0.f, s3 = 0.f, s4 = 0.f;
    for (int t = 0; t < DIM; t++) {
        float a = w1W[j * 2 * DIM + t];
        float c = combW[j * 2 * DIM + t];
        float ms = M2s[t * DIM + k];
        float mn = M2n[t * DIM + k];
        s1 += a * ms;  s2 += a * mn;
        s3 += c * ms;  s4 += c * mn;
    }
    G1[j * DIM + k] = __float2half_rn(s1);
    G2[j * DIM + k] = __float2half_rn(s2);
    X1[j * DIM + k] = __float2half_rn(s3);
    X2[j * DIM + k] = __float2half_rn(s4);
    if (k == 0) {
        float ba = 0.f, bc = 0.f;
        for (int t = 0; t < DIM; t++) {
            ba += w1W[j * 2 * DIM + t] * b2[t];
            bc += combW[j * 2 * DIM + t] * b2[t];
        }
        gb[j]   = ba + w1b[j];
        bout[j] = bc + bf[j];
    }
}

// ---------------- fp16 GEMM machinery ----------------
using FragAccH = wmma::fragment<wmma::accumulator, 16, 16, 16, float>;
using FragAh   = wmma::fragment<wmma::matrix_a, 16, 16, 16, __half, wmma::row_major>;
using FragBh   = wmma::fragment<wmma::matrix_b, 16, 16, 16, __half, wmma::col_major>;

#define GEMM_SMEM (4 * 128 * STH * (int)sizeof(__half))                          // 40960
#define MEGA_SMEM ((4 * 128 * STH + 2 * 128 * T_ST) * (int)sizeof(__half))       // 110592

__device__ __forceinline__ void cp_chunk(__half* __restrict__ As, __half* __restrict__ Wsm,
                                         const __half* __restrict__ A,
                                         const __half* __restrict__ W, int ldw,
                                         int kl, int row0, int N, int tid)
{
    #pragma unroll
    for (int it = 0; it < 2; it++) {
        int slot = tid + it * 256;
        int r = slot >> 2;
        int c8 = (slot & 3) * 8;
        const __half* ga = A + (size_t)(row0 + r) * DIM + kl + c8;
        uint32_t sa = (uint32_t)__cvta_generic_to_shared(As + r * STH + c8);
        int bytes = (row0 + r < N) ? 16 : 0;
        asm volatile("cp.async.cg.shared.global [%0], [%1], 16, %2;"
                     :: "r"(sa), "l"(ga), "r"(bytes));
        const __half* gw = W + (size_t)r * ldw + kl + c8;
        uint32_t sw = (uint32_t)__cvta_generic_to_shared(Wsm + r * STH + c8);
        asm volatile("cp.async.cg.shared.global [%0], [%1], 16;"
                     :: "r"(sw), "l"(gw));
    }
}

__device__ __forceinline__ void cp_w(__half* __restrict__ Wsm,
                                     const __half* __restrict__ W, int ldw,
                                     int kl, int tid)
{
    #pragma unroll
    for (int it = 0; it < 2; it++) {
        int slot = tid + it * 256;
        int r = slot >> 2;
        int c8 = (slot & 3) * 8;
        const __half* gw = W + (size_t)r * ldw + kl + c8;
        uint32_t sw = (uint32_t)__cvta_generic_to_shared(Wsm + r * STH + c8);
        asm volatile("cp.async.cg.shared.global [%0], [%1], 16;"
                     :: "r"(sw), "l"(gw));
    }
}

__device__ __forceinline__ void mma_step(FragAccH acc[4][2],
                                         const __half* Aa, int ldA,
                                         const __half* Wa, int wm, int wn)
{
    #pragma unroll
    for (int kf = 0; kf < 2; kf++) {
        FragAh af[4];
        FragBh bfr[2];
        #pragma unroll
        for (int mf = 0; mf < 4; mf++)
            wmma::load_matrix_sync(af[mf], Aa + (wm * 64 + mf * 16) * ldA + kf * 16, ldA);
        #pragma unroll
        for (int nf = 0; nf < 2; nf++)
            wmma::load_matrix_sync(bfr[nf], Wa + (wn * 32 + nf * 16) * STH + kf * 16, STH);
        #pragma unroll
        for (int mf = 0; mf < 4; mf++)
            #pragma unroll
            for (int nf = 0; nf < 2; nf++)
                wmma::mma_sync(acc[mf][nf], af[mf], bfr[nf], acc[mf][nf]);
    }
}

__device__ __forceinline__ void acc_zero(FragAccH acc[4][2]) {
    #pragma unroll
    for (int i = 0; i < 4; i++)
        #pragma unroll
        for (int j = 0; j < 2; j++) wmma::fill_fragment(acc[i][j], 0.0f);
}

template<int ACT>
__device__ __forceinline__ void epi(FragAccH acc[4][2], float* stg_base,
                                    const float* __restrict__ bias,
                                    __half* __restrict__ outh, __half* __restrict__ Tt,
                                    float* __restrict__ outf,
                                    int row0, int N, int warp, int lane, int wm, int wn)
{
    float* stg = stg_base + warp * 512;
    const float bj = bias[wn * 32 + lane];
    #pragma unroll
    for (int mf = 0; mf < 4; mf++) {
        wmma::store_matrix_sync(stg, acc[mf][0], 32, wmma::mem_row_major);
        wmma::store_matrix_sync(stg + 16, acc[mf][1], 32, wmma::mem_row_major);
        __syncwarp();
        #pragma unroll
        for (int r = 0; r < 16; r++) {
            int lr = wm * 64 + mf * 16 + r;
            int row = row0 + lr;
            float v = stg[r * 32 + lane] + bj;
            if (ACT == 1) v = fmaxf(v, 0.0f);
            else if (ACT == 2) v = (v >= 0.0f) ? v : 0.2f * v;
            if (Tt) Tt[lr * T_ST + wn * 32 + lane] = __float2half_rn(v);
            if (row < N) {
                if (outh) outh[(size_t)row * DIM + wn * 32 + lane] = __float2half_rn(v);
                if (outf) outf[(size_t)row * DIM + wn * 32 + lane] = v;
            }
        }
        __syncwarp();
    }
}

// ---------------- plain 2-term GEMM (for ii2) ----------------
__global__ void __launch_bounds__(256, 2) k_gemm2(
    const __half* __restrict__ A0, const __half* __restrict__ W0, int ldw0,
    const __half* __restrict__ A1, const __half* __restrict__ W1, int ldw1,
    const float* __restrict__ bias, __half* __restrict__ C, int N)
{
    extern __shared__ __align__(16) __half dynh[];
    __half* Abuf[2] = { dynh,                 dynh + 128 * STH };
    __half* Wbuf[2] = { dynh + 2 * 128 * STH, dynh + 3 * 128 * STH };
    const int tid = threadIdx.x, warp = tid >> 5, lane = tid & 31;
    const int row0 = blockIdx.x * 128, wm = warp >> 2, wn = warp & 3;

    FragAccH acc[4][2];
    acc_zero(acc);
    cp_chunk(Abuf[0], Wbuf[0], A0, W0, ldw0, 0, row0, N, tid);
    asm volatile("cp.async.commit_group;");
    for (int i = 0; i < 8; i++) {
        asm volatile("cp.async.wait_group 0;");
        __syncthreads();
        int buf = i & 1;
        if (i + 1 < 8) {
            int kg = (i + 1) * BK;
            const __half* A = (kg < 128) ? A0 : A1;
            const __half* W = (kg < 128) ? W0 : W1;
            int ldw = (kg < 128) ? ldw0 : ldw1;
            cp_chunk(Abuf[buf ^ 1], Wbuf[buf ^ 1], A, W, ldw, kg & 127, row0, N, tid);
            asm volatile("cp.async.commit_group;");
        }
        mma_step(acc, Abuf[buf], STH, Wbuf[buf], wm, wn);
        __syncthreads();
    }
    epi<0>(acc, (float*)dynh, bias, C, nullptr, nullptr, row0, N, warp, lane, wm, wn);
}

// ---------------- mega A: gather n1 + t0 + src ----------------
__global__ void __launch_bounds__(256, 2) k_megaA(
    const __half* __restrict__ ii2, const int* __restrict__ rowB,
    const int* __restrict__ cntB, const int* __restrict__ esrcB,
    const __half* __restrict__ eh, const __half* __restrict__ ekS,
    const __half* __restrict__ ekN, const float* __restrict__ ekb,
    const __half* __restrict__ G1, const __half* __restrict__ G2,
    const __half* __restrict__ w1b, int ldw1b, const float* __restrict__ gb,
    __half* __restrict__ n1g, __half* __restrict__ t0g, __half* __restrict__ srcg, int N)
{
    extern __shared__ __align__(16) __half dynh[];
    __half* Abuf[2] = { dynh,                 dynh + 128 * STH };
    __half* Wbuf[2] = { dynh + 2 * 128 * STH, dynh + 3 * 128 * STH };
    __half* Tt = dynh + 4 * 128 * STH;
    __half* Nt = Tt + 128 * T_ST;
    const int tid = threadIdx.x, warp = tid >> 5, lane = tid & 31;
    const int row0 = blockIdx.x * 128, wm = warp >> 2, wn = warp & 3;

    // ---- phase 0: gather n1 rows into Nt (+ gmem n1g) ----
    for (int rr = warp; rr < 128; rr += 8) {
        int row = row0 + rr;
        float a0 = 0.f, a1 = 0.f, a2 = 0.f, a3 = 0.f;
        if (row < N) {
            int s0 = __ldg(rowB + row);
            int c  = __ldg(cntB + row);
            int e = s0, end = s0 + c;
            for (; e + 3 < end; e += 4) {
                int sA = __ldg(esrcB + e),     sB = __ldg(esrcB + e + 1);
                int sC = __ldg(esrcB + e + 2), sD = __ldg(esrcB + e + 3);
                uint2 rA = __ldg((const uint2*)(ii2 + (size_t)sA * DIM) + lane);
                uint2 rB = __ldg((const uint2*)(ii2 + (size_t)sB * DIM) + lane);
                uint2 rC = __ldg((const uint2*)(ii2 + (size_t)sC * DIM) + lane);
                uint2 rD = __ldg((const uint2*)(ii2 + (size_t)sD * DIM) + lane);
                float2 fA0 = __half22float2(*(__half2*)&rA.x), fA1 = __half22float2(*(__half2*)&rA.y);
                float2 fB0 = __half22float2(*(__half2*)&rB.x), fB1 = __half22float2(*(__half2*)&rB.y);
                float2 fC0 = __half22float2(*(__half2*)&rC.x), fC1 = __half22float2(*(__half2*)&rC.y);
                float2 fD0 = __half22float2(*(__half2*)&rD.x), fD1 = __half22float2(*(__half2*)&rD.y);
                a0 += fA0.x + fB0.x + fC0.x + fD0.x;
                a1 += fA0.y + fB0.y + fC0.y + fD0.y;
                a2 += fA1.x + fB1.x + fC1.x + fD1.x;
                a3 += fA1.y + fB1.y + fC1.y + fD1.y;
            }
            for (; e < end; e++) {
                int s = __ldg(esrcB + e);
                uint2 r = __ldg((const uint2*)(ii2 + (size_t)s * DIM) + lane);
                float2 f0 = __half22float2(*(__half2*)&r.x), f1 = __half22float2(*(__half2*)&r.y);
                a0 += f0.x; a1 += f0.y; a2 += f1.x; a3 += f1.y;
            }
            float inv = 1.f / fmaxf((float)c, 1.f);
            a0 *= inv; a1 *= inv; a2 *= inv; a3 *= inv;
        }
        __half2 o0 = __floats2half2_rn(a0, a1);
        __half2 o1 = __floats2half2_rn(a2, a3);
        uint2 o;
        o.x = *(uint32_t*)&o0;
        o.y = *(uint32_t*)&o1;
        *((uint2*)(Nt + rr * T_ST) + lane) = o;
        if (row < N) *((uint2*)(n1g + (size_t)row * DIM) + lane) = o;
    }
    __syncthreads();

    FragAccH acc[4][2];
    // ---- phase 1: t0 = relu(e@ekS + Nt@ekN + ekb) -> Tt + t0g ----
    acc_zero(acc);
    cp_chunk(Abuf[0], Wbuf[0], eh, ekS, DIM, 0, row0, N, tid);
    asm volatile("cp.async.commit_group;");
    for (int i = 0; i < 8; i++) {
        asm volatile("cp.async.wait_group 0;");
        __syncthreads();
        int buf = i & 1;
        if (i + 1 < 8) {
            int i1 = i + 1;
            if (i1 < 4) cp_chunk(Abuf[i1 & 1], Wbuf[i1 & 1], eh, ekS, DIM, i1 * BK, row0, N, tid);
            else        cp_w(Wbuf[i1 & 1], ekN, DIM, (i1 - 4) * BK, tid);
            asm volatile("cp.async.commit_group;");
        }
        if (i < 4) mma_step(acc, Abuf[buf], STH, Wbuf[buf], wm, wn);
        else       mma_step(acc, Nt + (i - 4) * BK, T_ST, Wbuf[buf], wm, wn);
        __syncthreads();
    }
    epi<1>(acc, (float*)dynh, ekb, t0g, Tt, nullptr, row0, N, warp, lane, wm, wn);
    __syncthreads();

    // ---- phase 2: src = Tt@G1 + Nt@G2 + e@w1b + gb -> srcg ----
    acc_zero(acc);
    cp_w(Wbuf[0], G1, DIM, 0, tid);
    asm volatile("cp.async.commit_group;");
    for (int i = 0; i < 12; i++) {
        asm volatile("cp.async.wait_group 0;");
        __syncthreads();
        int buf = i & 1;
        if (i + 1 < 12) {
            int i1 = i + 1, term = i1 >> 2, kl = (i1 & 3) * BK;
            if (term == 0)      cp_w(Wbuf[i1 & 1], G1, DIM, kl, tid);
            else if (term == 1) cp_w(Wbuf[i1 & 1], G2, DIM, kl, tid);
            else                cp_chunk(Abuf[i1 & 1], Wbuf[i1 & 1], eh, w1b, ldw1b, kl, row0, N, tid);
            asm volatile("cp.async.commit_group;");
        }
        int term = i >> 2;
        if (term == 0)      mma_step(acc, Tt + (i & 3) * BK, T_ST, Wbuf[buf], wm, wn);
        else if (term == 1) mma_step(acc, Nt + (i & 3) * BK, T_ST, Wbuf[buf], wm, wn);
        else                mma_step(acc, Abuf[buf], STH, Wbuf[buf], wm, wn);
        __syncthreads();
    }
    epi<0>(acc, (float*)dynh, gb, srcg, nullptr, nullptr, row0, N, warp, lane, wm, wn);
}

// ---------------- mega B: gather n2 (smem only) + t1 + out ----------------
__global__ void __launch_bounds__(256, 2) k_megaB(
    const __half* __restrict__ srcc, const int* __restrict__ rowC,
    const int* __restrict__ cntC, const int2* __restrict__ epkC,
    const __half* __restrict__ eh, const __half* __restrict__ eeS,
    const __half* __restrict__ eeN, const float* __restrict__ eeb,
    const __half* __restrict__ F1, const __half* __restrict__ t0g,
    const __half* __restrict__ X1, const __half* __restrict__ n1g,
    const __half* __restrict__ X2, const __half* __restrict__ F2,
    const float* __restrict__ bout, float* __restrict__ outf, int N)
{
    extern __shared__ __align__(16) __half dynh[];
    __half* Abuf[2] = { dynh,                 dynh + 128 * STH };
    __half* Wbuf[2] = { dynh + 2 * 128 * STH, dynh + 3 * 128 * STH };
    __half* Tt = dynh + 4 * 128 * STH;
    __half* Nt = Tt + 128 * T_ST;
    const int tid = threadIdx.x, warp = tid >> 5, lane = tid & 31;
    const int row0 = blockIdx.x * 128, wm = warp >> 2, wn = warp & 3;

    // ---- phase 0: gather n2 rows into Nt (weighted, smem only) ----
    for (int rr = warp; rr < 128; rr += 8) {
        int row = row0 + rr;
        float a0 = 0.f, a1 = 0.f, a2 = 0.f, a3 = 0.f;
        if (row < N) {
            int s0 = __ldg(rowC + row);
            int c  = __ldg(cntC + row);
            int e = s0, end = s0 + c;
            for (; e + 3 < end; e += 4) {
                int2 pA = __ldg(epkC + e),     pB = __ldg(epkC + e + 1);
                int2 pC = __ldg(epkC + e + 2), pD = __ldg(epkC + e + 3);
                float wA = __int_as_float(pA.y), wB = __int_as_float(pB.y);
                float wC = __int_as_float(pC.y), wD = __int_as_float(pD.y);
                uint2 rA = __ldg((const uint2*)(srcc + (size_t)pA.x * DIM) + lane);
                uint2 rB = __ldg((const uint2*)(srcc + (size_t)pB.x * DIM) + lane);
                uint2 rC = __ldg((const uint2*)(srcc + (size_t)pC.x * DIM) + lane);
                uint2 rD = __ldg((const uint2*)(srcc + (size_t)pD.x * DIM) + lane);
                float2 fA0 = __half22float2(*(__half2*)&rA.x), fA1 = __half22float2(*(__half2*)&rA.y);
                float2 fB0 = __half22float2(*(__half2*)&rB.x), fB1 = __half22float2(*(__half2*)&rB.y);
                float2 fC0 = __half22float2(*(__half2*)&rC.x), fC1 = __half22float2(*(__half2*)&rC.y);
                float2 fD0 = __half22float2(*(__half2*)&rD.x), fD1 = __half22float2(*(__half2*)&rD.y);
                a0 += fA0.x * wA + fB0.x * wB + fC0.x * wC + fD0.x * wD;
                a1 += fA0.y * wA + fB0.y * wB + fC0.y * wC + fD0.y * wD;
                a2 += fA1.x * wA + fB1.x * wB + fC1.x * wC + fD1.x * wD;
                a3 += fA1.y * wA + fB1.y * wB + fC1.y * wC + fD1.y * wD;
            }
            for (; e < end; e++) {
                int2 p = __ldg(epkC + e);
                float w = __int_as_float(p.y);
                uint2 r = __ldg((const uint2*)(srcc + (size_t)p.x * DIM) + lane);
                float2 f0 = __half22float2(*(__half2*)&r.x), f1 = __half22float2(*(__half2*)&r.y);
                a0 += f0.x * w; a1 += f0.y * w; a2 += f1.x * w; a3 += f1.y * w;
            }
            float inv = 1.f / fmaxf((float)c, 1.f);
            a0 *= inv; a1 *= inv; a2 *= inv; a3 *= inv;
        }
        __half2 o0 = __floats2half2_rn(a0, a1);
        __half2 o1 = __floats2half2_rn(a2, a3);
        uint2 o;
        o.x = *(uint32_t*)&o0;
        o.y = *(uint32_t*)&o1;
        *((uint2*)(Nt + rr * T_ST) + lane) = o;
    }
    __syncthreads();

    FragAccH acc[4][2];
    // ---- phase 1: t1 = relu(e@eeS + Nt@eeN + eeb) -> Tt only ----
    acc_zero(acc);
    cp_chunk(Abuf[0], Wbuf[0], eh, eeS, DIM, 0, row0, N, tid);
    asm volatile("cp.async.commit_group;");
    for (int i = 0; i < 8; i++) {
        asm volatile("cp.async.wait_group 0;");
        __syncthreads();
        int buf = i & 1;
        if (i + 1 < 8) {
            int i1 = i + 1;
            if (i1 < 4) cp_chunk(Abuf[i1 & 1], Wbuf[i1 & 1], eh, eeS, DIM, i1 * BK, row0, N, tid);
            else        cp_w(Wbuf[i1 & 1], eeN, DIM, (i1 - 4) * BK, tid);
            asm volatile("cp.async.commit_group;");
        }
        if (i < 4) mma_step(acc, Abuf[buf], STH, Wbuf[buf], wm, wn);
        else       mma_step(acc, Nt + (i - 4) * BK, T_ST, Wbuf[buf], wm, wn);
        __syncthreads();
    }
    epi<1>(acc, (float*)dynh, eeb, nullptr, Tt, nullptr, row0, N, warp, lane, wm, wn);
    __syncthreads();

    // ---- phase 2: out = Tt@F1 + t0@X1 + n1@X2 + Nt@F2 + bout -> leaky float ----
    acc_zero(acc);
    cp_w(Wbuf[0], F1, DIM, 0, tid);
    asm volatile("cp.async.commit_group;");
    for (int i = 0; i < 16; i++) {
        asm volatile("cp.async.wait_group 0;");
        __syncthreads();
        int buf = i & 1;
        if (i + 1 < 16) {
            int i1 = i + 1, term = i1 >> 2, kl = (i1 & 3) * BK;
            if (term == 0)      cp_w(Wbuf[i1 & 1], F1, DIM, kl, tid);
            else if (term == 1) cp_chunk(Abuf[i1 & 1], Wbuf[i1 & 1], t0g, X1, DIM, kl, row0, N, tid);
            else if (term == 2) cp_chunk(Abuf[i1 & 1], Wbuf[i1 & 1], n1g, X2, DIM, kl, row0, N, tid);
            else                cp_w(Wbuf[i1 & 1], F2, DIM, kl, tid);
            asm volatile("cp.async.commit_group;");
        }
        int term = i >> 2;
        if (term == 0)      mma_step(acc, Tt + (i & 3) * BK, T_ST, Wbuf[buf], wm, wn);
        else if (term == 3) mma_step(acc, Nt + (i & 3) * BK, T_ST, Wbuf[buf], wm, wn);
        else                mma_step(acc, Abuf[buf], STH, Wbuf[buf], wm, wn);
        __syncthreads();
    }
    epi<2>(acc, (float*)dynh, bout, nullptr, nullptr, outf, row0, N, warp, lane, wm, wn);
}

// ---------------- driver ----------------
extern "C" void kernel_launch(void* const* d_in, const int* in_sizes, int n_in,
                              void* d_out, int out_size)
{
    const float* ii    = (const float*)d_in[0];
    const float* e_emb = (const float*)d_in[1];
    const float* kemb  = (const float*)d_in[2];
    const float* cf_ew = (const float*)d_in[3];
    const int*   b_src = (const int*)d_in[4];
    const int*   b_dst = (const int*)d_in[5];
    const int*   c_src = (const int*)d_in[6];
    const int*   c_dst = (const int*)d_in[7];
    const float* ekS = (const float*)d_in[8];
    const float* ekN = (const float*)d_in[9];
    const float* ekb = (const float*)d_in[10];
    const float* eeS = (const float*)d_in[11];
    const float* eeN = (const float*)d_in[12];
    const float* eeb = (const float*)d_in[13];
    const float* w1W = (const float*)d_in[14];
    const float* w1b = (const float*)d_in[15];
    const float* w2W = (const float*)d_in[16];
    const float* w2b = (const float*)d_in[17];
    const float* w3W = (const float*)d_in[18];
    const float* w3b = (const float*)d_in[19];
    const float* w4W = (const float*)d_in[20];
    const float* w4b = (const float*)d_in[21];
    const float* cW  = (const float*)d_in[22];
    const float* cb  = (const float*)d_in[23];
    float* out = (float*)d_out;

    const int n_k = in_sizes[0] / DIM;
    const int n_e = in_sizes[1] / DIM;
    const int Eb  = in_sizes[4];
    const int Ec  = in_sizes[6];

    __half *eh, *ii2, *iih, *keh, *n1, *t0, *srcc;
    __half *w4h, *w1h, *ekSh, *ekNh, *eeSh, *eeNh, *G1, *G2, *X1, *X2, *F1, *F2;
    float *M2s, *M2n, *P, *b2, *bfv, *gb, *bout;
    int *cntB, *rowB, *curB, *choffB, *esrcB;
    int *cntC, *rowC, *curC, *choffC;
    int2 *epkC;
    cudaGetSymbolAddress((void**)&eh,    g_eh);
    cudaGetSymbolAddress((void**)&ii2,   g_ii2);
    cudaGetSymbolAddress((void**)&iih,   g_iih);
    cudaGetSymbolAddress((void**)&keh,   g_keh);
    cudaGetSymbolAddress((void**)&n1,    g_n1);
    cudaGetSymbolAddress((void**)&t0,    g_t0);
    cudaGetSymbolAddress((void**)&srcc,  g_srcc);
    cudaGetSymbolAddress((void**)&w4h,   g_w4h);
    cudaGetSymbolAddress((void**)&w1h,   g_w1h);
    cudaGetSymbolAddress((void**)&ekSh,  g_ekSh);
    cudaGetSymbolAddress((void**)&ekNh,  g_ekNh);
    cudaGetSymbolAddress((void**)&eeSh,  g_eeSh);
    cudaGetSymbolAddress((void**)&eeNh,  g_eeNh);
    cudaGetSymbolAddress((void**)&G1,    g_G1);
    cudaGetSymbolAddress((void**)&G2,    g_G2);
    cudaGetSymbolAddress((void**)&X1,    g_X1);
    cudaGetSymbolAddress((void**)&X2,    g_X2);
    cudaGetSymbolAddress((void**)&F1,    g_F1);
    cudaGetSymbolAddress((void**)&F2,    g_F2);
    cudaGetSymbolAddress((void**)&M2s,   g_M2s);
    cudaGetSymbolAddress((void**)&M2n,   g_M2n);
    cudaGetSymbolAddress((void**)&P,     g_P);
    cudaGetSymbolAddress((void**)&b2,    g_b2);
    cudaGetSymbolAddress((void**)&bfv,   g_bf);
    cudaGetSymbolAddress((void**)&gb,    g_gb);
    cudaGetSymbolAddress((void**)&bout,  g_bout);
    cudaGetSymbolAddress((void**)&cntB,  g_cntB);
    cudaGetSymbolAddress((void**)&rowB,  g_rowB);
    cudaGetSymbolAddress((void**)&curB,  g_curB);
    cudaGetSymbolAddress((void**)&choffB,g_choffB);
    cudaGetSymbolAddress((void**)&esrcB, g_esrcB);
    cudaGetSymbolAddress((void**)&cntC,  g_cntC);
    cudaGetSymbolAddress((void**)&rowC,  g_rowC);
    cudaGetSymbolAddress((void**)&curC,  g_curC);
    cudaGetSymbolAddress((void**)&choffC,g_choffC);
    cudaGetSymbolAddress((void**)&epkC,  g_epkC);

    static cudaStream_t sB = nullptr, sC = nullptr;
    static cudaEvent_t ev0 = nullptr, evB = nullptr, evCombo = nullptr, evC = nullptr;
    static bool init_done = false;
    if (!init_done) {
        cudaFuncSetAttribute(k_gemm2, cudaFuncAttributeMaxDynamicSharedMemorySize, GEMM_SMEM);
        cudaFuncSetAttribute(k_megaA, cudaFuncAttributeMaxDynamicSharedMemorySize, MEGA_SMEM);
        cudaFuncSetAttribute(k_megaB, cudaFuncAttributeMaxDynamicSharedMemorySize, MEGA_SMEM);
        cudaStreamCreateWithFlags(&sB, cudaStreamNonBlocking);
        cudaStreamCreateWithFlags(&sC, cudaStreamNonBlocking);
        cudaEventCreateWithFlags(&ev0,     cudaEventDisableTiming);
        cudaEventCreateWithFlags(&evB,     cudaEventDisableTiming);
        cudaEventCreateWithFlags(&evCombo, cudaEventDisableTiming);
        cudaEventCreateWithFlags(&evC,     cudaEventDisableTiming);
        init_done = true;
    }

    const int gNe = (n_e + 127) / 128;
    const int gNk = (n_k + 127) / 128;
    const int nchunks = (n_e + SCAN_CHUNK - 1) / SCAN_CHUNK;

    // ---- fork ----
    cudaEventRecord(ev0, 0);
    cudaStreamWaitEvent(sB, ev0, 0);
    cudaStreamWaitEvent(sC, ev0, 0);

    // ---- stream B: belong CSR ----
    cudaMemsetAsync(cntB, 0, n_e * sizeof(int), sB);
    k_hist<<<(Eb + 255) / 256, 256, 0, sB>>>(b_dst, cntB, Eb);
    k_scan1<<<nchunks, 256, 0, sB>>>(cntB, rowB, choffB + 128, n_e);
    k_scan2<<<1, 256, 0, sB>>>(choffB + 128, choffB, nchunks);
    k_scan3<<<(n_e + 255) / 256, 256, 0, sB>>>(rowB, curB, choffB, n_e);
    k_scatter<<<(Eb + 255) / 256, 256, 0, sB>>>(b_src, b_dst, curB, esrcB, Eb);
    cudaEventRecord(evB, sB);

    // ---- stream C: conversions + folds + collab CSR ----
    k_f2h<<<(n_e * DIM / 4 + 255) / 256, 256, 0, sC>>>(eh, e_emb, n_e * DIM / 4);
    k_f2h<<<(DIM * DIM / 4 + 255) / 256, 256, 0, sC>>>(ekSh, ekS, DIM * DIM / 4);
    k_f2h<<<(DIM * DIM / 4 + 255) / 256, 256, 0, sC>>>(ekNh, ekN, DIM * DIM / 4);
    k_f2h<<<(DIM * DIM / 4 + 255) / 256, 256, 0, sC>>>(eeSh, eeS, DIM * DIM / 4);
    k_f2h<<<(DIM * DIM / 4 + 255) / 256, 256, 0, sC>>>(eeNh, eeN, DIM * DIM / 4);
    k_f2h<<<(2 * DIM * DIM / 4 + 255) / 256, 256, 0, sC>>>(w1h, w1W, 2 * DIM * DIM / 4);
    k_combo1<<<DIM, DIM, 0, sC>>>(w2W, w2b, ekS, ekN, ekb, cW, w3W, M2s, M2n, b2, P);
    k_combo2<<<DIM, DIM, 0, sC>>>(P, eeS, eeN, eeb, cW, w3b, cb, F1, F2, bfv);
    k_combo3<<<DIM, DIM, 0, sC>>>(w1W, w1b, cW, M2s, M2n, b2, bfv,
                                  G1, G2, X1, X2, gb, bout);
    cudaEventRecord(evCombo, sC);
    cudaMemsetAsync(cntC, 0, n_e * sizeof(int), sC);
    k_hist<<<(Ec + 255) / 256, 256, 0, sC>>>(c_dst, cntC, Ec);
    k_scan1<<<nchunks, 256, 0, sC>>>(cntC, rowC, choffC + 128, n_e);
    k_scan2<<<1, 256, 0, sC>>>(choffC + 128, choffC, nchunks);
    k_scan3<<<(n_e + 255) / 256, 256, 0, sC>>>(rowC, curC, choffC, n_e);
    k_scatter_p<<<(Ec + 255) / 256, 256, 0, sC>>>(c_src, c_dst, cf_ew, curC, epkC, Ec);
    cudaEventRecord(evC, sC);

    // ---- main stream ----
    k_f2h<<<(n_k * DIM / 4 + 255) / 256, 256>>>(iih, ii, n_k * DIM / 4);
    k_f2h<<<(n_k * DIM / 4 + 255) / 256, 256>>>(keh, kemb, n_k * DIM / 4);
    k_f2h<<<(2 * DIM * DIM / 4 + 255) / 256, 256>>>(w4h, w4W, 2 * DIM * DIM / 4);
    k_gemm2<<<gNk, 256, GEMM_SMEM>>>(iih, w4h, 2 * DIM, keh, w4h + DIM, 2 * DIM,
                                     w4b, ii2, n_k);

    // mega A: gather n1 + t0 + src  (needs CSR-B, ii2, combos)
    cudaStreamWaitEvent(0, evB, 0);
    cudaStreamWaitEvent(0, evCombo, 0);
    k_megaA<<<gNe, 256, MEGA_SMEM>>>(ii2, rowB, cntB, esrcB,
                                     eh, ekSh, ekNh, ekb,
                                     G1, G2, w1h + DIM, 2 * DIM, gb,
                                     n1, t0, srcc, n_e);

    // mega B: gather n2 + t1 + out  (needs CSR-C, srcc)
    cudaStreamWaitEvent(0, evC, 0);
    k_megaB<<<gNe, 256, MEGA_SMEM>>>(srcc, rowC, cntC, epkC,
                                     eh, eeSh, eeNh, eeb,
                                     F1, t0, X1, n1, X2, F2,
                                     bout, out, n_e);
}

// round 15
// speedup vs baseline: 1.4475x; 1.4475x over previous
#include <cuda_runtime.h>
#include <cuda_fp16.h>
#include <mma.h>
#include <cstdint>

using namespace nvcuda;

#define DIM 128
#define N_K_MAX 10000
#define N_E_MAX 100000
#define E_MAX   2000000
#define SCAN_CHUNK 1024
#define BK 32
#define STH 40    // stage-buffer row stride (halfs)
#define T_ST 136  // smem t-tile row stride (halfs)

// ---------------- scratch (static device globals; no allocation) ----------------
__device__ __half g_eh[N_E_MAX * DIM];
__device__ __half g_ii2[N_K_MAX * DIM];
__device__ __half g_iih[N_K_MAX * DIM];
__device__ __half g_keh[N_K_MAX * DIM];
__device__ __half g_n1[N_E_MAX * DIM];
__device__ __half g_n2[N_E_MAX * DIM];
__device__ __half g_t0[N_E_MAX * DIM];
__device__ __half g_srcc[N_E_MAX * DIM];
// half weights
__device__ __half g_w4h[DIM * 2 * DIM];
__device__ __half g_w1h[DIM * 2 * DIM];
__device__ __half g_ekSh[DIM * DIM], g_ekNh[DIM * DIM];
__device__ __half g_eeSh[DIM * DIM], g_eeNh[DIM * DIM];
__device__ __half g_G1[DIM * DIM], g_G2[DIM * DIM];
__device__ __half g_X1[DIM * DIM], g_X2[DIM * DIM];
__device__ __half g_F1[DIM * DIM], g_F2[DIM * DIM];
// fp32 fold intermediates + biases
__device__ float g_M2s[DIM * DIM], g_M2n[DIM * DIM], g_P[DIM * DIM];
__device__ float g_b2[DIM], g_bf[DIM], g_gb[DIM], g_bout[DIM];
// belong CSR
__device__ int   g_cntB[N_E_MAX];
__device__ int   g_rowB[N_E_MAX];
__device__ int   g_curB[N_E_MAX];
__device__ int   g_choffB[256];
__device__ int   g_esrcB[E_MAX];
// collab CSR (packed src+ew)
__device__ int   g_cntC[N_E_MAX];
__device__ int   g_rowC[N_E_MAX];
__device__ int   g_curC[N_E_MAX];
__device__ int   g_choffC[256];
__device__ int2  g_epkC[E_MAX];

// ---------------- float -> half conversion ----------------
__global__ void k_f2h(__half* __restrict__ dst, const float* __restrict__ src, int n4) {
    int i = blockIdx.x * blockDim.x + threadIdx.x;
    if (i >= n4) return;
    float4 v = ((const float4*)src)[i];
    __half2 h0 = __floats2half2_rn(v.x, v.y);
    __half2 h1 = __floats2half2_rn(v.z, v.w);
    uint2 u;
    u.x = *(uint32_t*)&h0;
    u.y = *(uint32_t*)&h1;
    ((uint2*)dst)[i] = u;
}

// ---------------- CSR build ----------------
__global__ void k_hist(const int* __restrict__ didx, int* __restrict__ cnt, int E) {
    int i = blockIdx.x * blockDim.x + threadIdx.x;
    if (i < E) atomicAdd(cnt + __ldg(didx + i), 1);
}

__global__ void k_scan1(const int* __restrict__ cnt, int* __restrict__ excl,
                        int* __restrict__ sums, int n) {
    __shared__ int warp_sums[8];
    int t = threadIdx.x;
    int lane = t & 31, w = t >> 5;
    int idx = blockIdx.x * SCAN_CHUNK + t * 4;
    int a0 = 0, a1 = 0, a2 = 0, a3 = 0;
    if (idx + 3 < n) {
        int4 v = *(const int4*)(cnt + idx);
        a0 = v.x; a1 = v.y; a2 = v.z; a3 = v.w;
    } else {
        if (idx + 0 < n) a0 = cnt[idx + 0];
        if (idx + 1 < n) a1 = cnt[idx + 1];
        if (idx + 2 < n) a2 = cnt[idx + 2];
        if (idx + 3 < n) a3 = cnt[idx + 3];
    }
    int s0 = a0, s1 = s0 + a1, s2 = s1 + a2, s3 = s2 + a3;
    int tot = s3;
    int x = tot;
    #pragma unroll
    for (int o = 1; o < 32; o <<= 1) {
        int y = __shfl_up_sync(0xffffffffu, x, o);
        if (lane >= o) x += y;
    }
    if (lane == 31) warp_sums[w] = x;
    __syncthreads();
    if (w == 0) {
        int y = (lane < 8) ? warp_sums[lane] : 0;
        #pragma unroll
        for (int o = 1; o < 8; o <<= 1) {
            int z = __shfl_up_sync(0xffffffffu, y, o);
            if (lane >= o) y += z;
        }
        if (lane < 8) warp_sums[lane] = y;
    }
    __syncthreads();
    int base = ((w > 0) ? warp_sums[w - 1] : 0) + (x - tot);
    if (idx + 0 < n) excl[idx + 0] = base;
    if (idx + 1 < n) excl[idx + 1] = base + s0;
    if (idx + 2 < n) excl[idx + 2] = base + s1;
    if (idx + 3 < n) excl[idx + 3] = base + s2;
    if (t == 0) sums[blockIdx.x] = warp_sums[7];
}

__global__ void k_scan2(const int* __restrict__ sums, int* __restrict__ off, int nchunks) {
    __shared__ int sh[256];
    int t = threadIdx.x;
    sh[t] = (t < nchunks) ? sums[t] : 0;
    __syncthreads();
    for (int o = 1; o < 256; o <<= 1) {
        int v = (t >= o) ? sh[t - o] : 0;
        __syncthreads();
        sh[t] += v;
        __syncthreads();
    }
    if (t < nchunks) off[t] = (t == 0) ? 0 : sh[t - 1];
}

__global__ void k_scan3(int* __restrict__ excl, int* __restrict__ cursor,
                        const int* __restrict__ off, int n) {
    int i = blockIdx.x * blockDim.x + threadIdx.x;
    if (i >= n) return;
    int v = excl[i] + off[i / SCAN_CHUNK];
    excl[i] = v;
    cursor[i] = v;
}

__global__ void k_scatter(const int* __restrict__ sidx, const int* __restrict__ didx,
                          int* __restrict__ cursor, int* __restrict__ esrc, int E) {
    int i = blockIdx.x * blockDim.x + threadIdx.x;
    if (i >= E) return;
    int d = __ldg(didx + i);
    int pos = atomicAdd(cursor + d, 1);
    esrc[pos] = __ldg(sidx + i);
}

__global__ void k_scatter_p(const int* __restrict__ sidx, const int* __restrict__ didx,
                            const float* __restrict__ ew, int* __restrict__ cursor,
                            int2* __restrict__ epk, int E) {
    int i = blockIdx.x * blockDim.x + threadIdx.x;
    if (i >= E) return;
    int d = __ldg(didx + i);
    int pos = atomicAdd(cursor + d, 1);
    epk[pos] = make_int2(__ldg(sidx + i), __float_as_int(__ldg(ew + i)));
}

// ---------------- gather aggregation (half src, half out, fp32 accum) ----------------
__global__ void __launch_bounds__(256) k_agg(
    const __half* __restrict__ src, const int* __restrict__ rowstart,
    const int* __restrict__ cnt, const int* __restrict__ esrc,
    __half* __restrict__ out, int n)
{
    int row = (blockIdx.x * blockDim.x + threadIdx.x) >> 5;
    int lane = threadIdx.x & 31;
    if (row >= n) return;
    int s0 = __ldg(rowstart + row);
    int c  = __ldg(cnt + row);
    float a0 = 0.f, a1 = 0.f, a2 = 0.f, a3 = 0.f;
    int e = s0, end = s0 + c;
    for (; e + 3 < end; e += 4) {
        int sA = __ldg(esrc + e),     sB = __ldg(esrc + e + 1);
        int sC = __ldg(esrc + e + 2), sD = __ldg(esrc + e + 3);
        uint2 rA = __ldg((const uint2*)(src + (size_t)sA * DIM) + lane);
        uint2 rB = __ldg((const uint2*)(src + (size_t)sB * DIM) + lane);
        uint2 rC = __ldg((const uint2*)(src + (size_t)sC * DIM) + lane);
        uint2 rD = __ldg((const uint2*)(src + (size_t)sD * DIM) + lane);
        float2 fA0 = __half22float2(*(__half2*)&rA.x), fA1 = __half22float2(*(__half2*)&rA.y);
        float2 fB0 = __half22float2(*(__half2*)&rB.x), fB1 = __half22float2(*(__half2*)&rB.y);
        float2 fC0 = __half22float2(*(__half2*)&rC.x), fC1 = __half22float2(*(__half2*)&rC.y);
        float2 fD0 = __half22float2(*(__half2*)&rD.x), fD1 = __half22float2(*(__half2*)&rD.y);
        a0 += fA0.x + fB0.x + fC0.x + fD0.x;
        a1 += fA0.y + fB0.y + fC0.y + fD0.y;
        a2 += fA1.x + fB1.x + fC1.x + fD1.x;
        a3 += fA1.y + fB1.y + fC1.y + fD1.y;
    }
    for (; e < end; e++) {
        int s = __ldg(esrc + e);
        uint2 r = __ldg((const uint2*)(src + (size_t)s * DIM) + lane);
        float2 f0 = __half22float2(*(__half2*)&r.x), f1 = __half22float2(*(__half2*)&r.y);
        a0 += f0.x; a1 += f0.y; a2 += f1.x; a3 += f1.y;
    }
    float inv = 1.f / fmaxf((float)c, 1.f);
    __half2 o0 = __floats2half2_rn(a0 * inv, a1 * inv);
    __half2 o1 = __floats2half2_rn(a2 * inv, a3 * inv);
    uint2 o;
    o.x = *(uint32_t*)&o0;
    o.y = *(uint32_t*)&o1;
    ((uint2*)(out + (size_t)row * DIM))[lane] = o;
}

__global__ void __launch_bounds__(256) k_agg_p(
    const __half* __restrict__ src, const int* __restrict__ rowstart,
    const int* __restrict__ cnt, const int2* __restrict__ epk,
    __half* __restrict__ out, int n)
{
    int row = (blockIdx.x * blockDim.x + threadIdx.x) >> 5;
    int lane = threadIdx.x & 31;
    if (row >= n) return;
    int s0 = __ldg(rowstart + row);
    int c  = __ldg(cnt + row);
    float a0 = 0.f, a1 = 0.f, a2 = 0.f, a3 = 0.f;
    int e = s0, end = s0 + c;
    for (; e + 3 < end; e += 4) {
        int2 pA = __ldg(epk + e),     pB = __ldg(epk + e + 1);
        int2 pC = __ldg(epk + e + 2), pD = __ldg(epk + e + 3);
        float wA = __int_as_float(pA.y), wB = __int_as_float(pB.y);
        float wC = __int_as_float(pC.y), wD = __int_as_float(pD.y);
        uint2 rA = __ldg((const uint2*)(src + (size_t)pA.x * DIM) + lane);
        uint2 rB = __ldg((const uint2*)(src + (size_t)pB.x * DIM) + lane);
        uint2 rC = __ldg((const uint2*)(src + (size_t)pC.x * DIM) + lane);
        uint2 rD = __ldg((const uint2*)(src + (size_t)pD.x * DIM) + lane);
        float2 fA0 = __half22float2(*(__half2*)&rA.x), fA1 = __half22float2(*(__half2*)&rA.y);
        float2 fB0 = __half22float2(*(__half2*)&rB.x), fB1 = __half22float2(*(__half2*)&rB.y);
        float2 fC0 = __half22float2(*(__half2*)&rC.x), fC1 = __half22float2(*(__half2*)&rC.y);
        float2 fD0 = __half22float2(*(__half2*)&rD.x), fD1 = __half22float2(*(__half2*)&rD.y);
        a0 += fA0.x * wA + fB0.x * wB + fC0.x * wC + fD0.x * wD;
        a1 += fA0.y * wA + fB0.y * wB + fC0.y * wC + fD0.y * wD;
        a2 += fA1.x * wA + fB1.x * wB + fC1.x * wC + fD1.x * wD;
        a3 += fA1.y * wA + fB1.y * wB + fC1.y * wC + fD1.y * wD;
    }
    for (; e < end; e++) {
        int2 p = __ldg(epk + e);
        float w = __int_as_float(p.y);
        uint2 r = __ldg((const uint2*)(src + (size_t)p.x * DIM) + lane);
        float2 f0 = __half22float2(*(__half2*)&r.x), f1 = __half22float2(*(__half2*)&r.y);
        a0 += f0.x * w; a1 += f0.y * w; a2 += f1.x * w; a3 += f1.y * w;
    }
    float inv = 1.f / fmaxf((float)c, 1.f);
    __half2 o0 = __floats2half2_rn(a0 * inv, a1 * inv);
    __half2 o1 = __floats2half2_rn(a2 * inv, a3 * inv);
    uint2 o;
    o.x = *(uint32_t*)&o0;
    o.y = *(uint32_t*)&o1;
    ((uint2*)(out + (size_t)row * DIM))[lane] = o;
}

// ---------------- weight folding (exact fp32 fold; half outputs for GEMM weights) ----------------
__global__ void k_combo1(const float* __restrict__ w2, const float* __restrict__ w2b,
                         const float* __restrict__ ekS, const float* __restrict__ ekN,
                         const float* __restrict__ ekb,
                         const float* __restrict__ combW, const float* __restrict__ w3,
                         float* __restrict__ M2s, float* __restrict__ M2n,
                         float* __restrict__ b2, float* __restrict__ P)
{
    int j = blockIdx.x, k = threadIdx.x;
    const float* ekS1 = ekS + DIM * DIM;
    const float* ekN1 = ekN + DIM * DIM;
    const float* ekb1 = ekb + DIM;
    float s1 = 0.f, s2 = 0.f, s3 = 0.f;
    for (int t = 0; t < DIM; t++) {
        float a = w2[j * DIM + t];
        s1 += a * ekS1[t * DIM + k];
        s2 += a * ekN1[t * DIM + k];
        float cbv = combW[j * 2 * DIM + DIM + t];
        s3 += cbv * w3[t * DIM + k];
    }
    M2s[j * DIM + k] = s1;
    M2n[j * DIM + k] = s2;
    P[j * DIM + k] = s3;
    if (k == 0) {
        float b = 0.f;
        for (int t = 0; t < DIM; t++) b += w2[j * DIM + t] * ekb1[t];
        b2[j] = b + w2b[j];
    }
}

__global__ void k_combo2(const float* __restrict__ P,
                         const float* __restrict__ eeS, const float* __restrict__ eeN,
                         const float* __restrict__ eeb,
                         const float* __restrict__ combW, const float* __restrict__ w3b,
                         const float* __restrict__ combb,
                         __half* __restrict__ F1, __half* __restrict__ F2,
                         float* __restrict__ bf)
{
    int j = blockIdx.x, k = threadIdx.x;
    const float* eeS1 = eeS + DIM * DIM;
    const float* eeN1 = eeN + DIM * DIM;
    const float* eeb1 = eeb + DIM;
    float s1 = 0.f, s2 = 0.f;
    for (int t = 0; t < DIM; t++) {
        float p = P[j * DIM + t];
        s1 += p * eeS1[t * DIM + k];
        s2 += p * eeN1[t * DIM + k];
    }
    F1[j * DIM + k] = __float2half_rn(s1);
    F2[j * DIM + k] = __float2half_rn(s2);
    if (k == 0) {
        float b = 0.f;
        for (int t = 0; t < DIM; t++)
            b += P[j * DIM + t] * eeb1[t] + combW[j * 2 * DIM + DIM + t] * w3b[t];
        bf[j] = b + combb[j];
    }
}

__global__ void k_combo3(const float* __restrict__ w1W, const float* __restrict__ w1b,
                         const float* __restrict__ combW,
                         const float* __restrict__ M2s, const float* __restrict__ M2n,
                         const float* __restrict__ b2, const float* __restrict__ bf,
                         __half* __restrict__ G1, __half* __restrict__ G2,
                         __half* __restrict__ X1, __half* __restrict__ X2,
                         float* __restrict__ gb, float* __restrict__ bout)
{
    int j = blockIdx.x, k = threadIdx.x;
    float s1 = 0.f, s2 = 0.f, s3 = 0.f, s4 = 0.f;
    for (int t = 0; t < DIM; t++) {
        float a = w1W[j * 2 * DIM + t];
        float c = combW[j * 2 * DIM + t];
        float ms = M2s[t * DIM + k];
        float mn = M2n[t * DIM + k];
        s1 += a * ms;  s2 += a * mn;
        s3 += c * ms;  s4 += c * mn;
    }
    G1[j * DIM + k] = __float2half_rn(s1);
    G2[j * DIM + k] = __float2half_rn(s2);
    X1[j * DIM + k] = __float2half_rn(s3);
    X2[j * DIM + k] = __float2half_rn(s4);
    if (k == 0) {
        float ba = 0.f, bc = 0.f;
        for (int t = 0; t < DIM; t++) {
            ba += w1W[j * 2 * DIM + t] * b2[t];
            bc += combW[j * 2 * DIM + t] * b2[t];
        }
        gb[j]   = ba + w1b[j];
        bout[j] = bc + bf[j];
    }
}

// ---------------- fp16 GEMM machinery (3-stage pipeline) ----------------
using FragAccH = wmma::fragment<wmma::accumulator, 16, 16, 16, float>;
using FragAh   = wmma::fragment<wmma::matrix_a, 16, 16, 16, __half, wmma::row_major>;
using FragBh   = wmma::fragment<wmma::matrix_b, 16, 16, 16, __half, wmma::col_major>;

#define GEMM_SMEM  (6 * 128 * STH * (int)sizeof(__half))                    // 61440
#define FUSED_SMEM ((6 * 128 * STH + 128 * T_ST) * (int)sizeof(__half))     // 96256

__device__ __forceinline__ void cp_chunk(__half* __restrict__ As, __half* __restrict__ Wsm,
                                         const __half* __restrict__ A,
                                         const __half* __restrict__ W, int ldw,
                                         int kl, int row0, int N, int tid)
{
    #pragma unroll
    for (int it = 0; it < 2; it++) {
        int slot = tid + it * 256;
        int r = slot >> 2;
        int c8 = (slot & 3) * 8;
        const __half* ga = A + (size_t)(row0 + r) * DIM + kl + c8;
        uint32_t sa = (uint32_t)__cvta_generic_to_shared(As + r * STH + c8);
        int bytes = (row0 + r < N) ? 16 : 0;
        asm volatile("cp.async.cg.shared.global [%0], [%1], 16, %2;"
                     :: "r"(sa), "l"(ga), "r"(bytes));
        const __half* gw = W + (size_t)r * ldw + kl + c8;
        uint32_t sw = (uint32_t)__cvta_generic_to_shared(Wsm + r * STH + c8);
        asm volatile("cp.async.cg.shared.global [%0], [%1], 16;"
                     :: "r"(sw), "l"(gw));
    }
}

__device__ __forceinline__ void cp_w(__half* __restrict__ Wsm,
                                     const __half* __restrict__ W, int ldw,
                                     int kl, int tid)
{
    #pragma unroll
    for (int it = 0; it < 2; it++) {
        int slot = tid + it * 256;
        int r = slot >> 2;
        int c8 = (slot & 3) * 8;
        const __half* gw = W + (size_t)r * ldw + kl + c8;
        uint32_t sw = (uint32_t)__cvta_generic_to_shared(Wsm + r * STH + c8);
        asm volatile("cp.async.cg.shared.global [%0], [%1], 16;"
                     :: "r"(sw), "l"(gw));
    }
}

__device__ __forceinline__ void mma_step(FragAccH acc[4][2],
                                         const __half* Aa, int ldA,
                                         const __half* Wa, int wm, int wn)
{
    #pragma unroll
    for (int kf = 0; kf < 2; kf++) {
        FragAh af[4];
        FragBh bfr[2];
        #pragma unroll
        for (int mf = 0; mf < 4; mf++)
            wmma::load_matrix_sync(af[mf], Aa + (wm * 64 + mf * 16) * ldA + kf * 16, ldA);
        #pragma unroll
        for (int nf = 0; nf < 2; nf++)
            wmma::load_matrix_sync(bfr[nf], Wa + (wn * 32 + nf * 16) * STH + kf * 16, STH);
        #pragma unroll
        for (int mf = 0; mf < 4; mf++)
            #pragma unroll
            for (int nf = 0; nf < 2; nf++)
                wmma::mma_sync(acc[mf][nf], af[mf], bfr[nf], acc[mf][nf]);
    }
}

__device__ __forceinline__ void acc_zero(FragAccH acc[4][2]) {
    #pragma unroll
    for (int i = 0; i < 4; i++)
        #pragma unroll
        for (int j = 0; j < 2; j++) wmma::fill_fragment(acc[i][j], 0.0f);
}

template<int ACT>
__device__ __forceinline__ void epi(FragAccH acc[4][2], float* stg_base,
                                    const float* __restrict__ bias,
                                    __half* __restrict__ outh, __half* __restrict__ Tt,
                                    float* __restrict__ outf,
                                    int row0, int N, int warp, int lane, int wm, int wn)
{
    float* stg = stg_base + warp * 512;
    const float bj = bias[wn * 32 + lane];
    #pragma unroll
    for (int mf = 0; mf < 4; mf++) {
        wmma::store_matrix_sync(stg, acc[mf][0], 32, wmma::mem_row_major);
        wmma::store_matrix_sync(stg + 16, acc[mf][1], 32, wmma::mem_row_major);
        __syncwarp();
        #pragma unroll
        for (int r = 0; r < 16; r++) {
            int lr = wm * 64 + mf * 16 + r;
            int row = row0 + lr;
            float v = stg[r * 32 + lane] + bj;
            if (ACT == 1) v = fmaxf(v, 0.0f);
            else if (ACT == 2) v = (v >= 0.0f) ? v : 0.2f * v;
            if (Tt) Tt[lr * T_ST + wn * 32 + lane] = __float2half_rn(v);
            if (row < N) {
                if (outh) outh[(size_t)row * DIM + wn * 32 + lane] = __float2half_rn(v);
                if (outf) outf[(size_t)row * DIM + wn * 32 + lane] = v;
            }
        }
        __syncwarp();
    }
}

// 3-stage pipelined pass over `total` chunks.
// ISSUE(c, b): issue loads for chunk c into buffer slot b.  MMA(c, b): compute chunk c.
#define PIPE3(total, ISSUE, MMA)                                             \
    {                                                                        \
        ISSUE(0, 0);                                                         \
        asm volatile("cp.async.commit_group;");                              \
        if ((total) > 1) { ISSUE(1, 1); }                                    \
        asm volatile("cp.async.commit_group;");                              \
        for (int i = 0; i < (total); i++) {                                  \
            if (i + 1 < (total)) asm volatile("cp.async.wait_group 1;");     \
            else                 asm volatile("cp.async.wait_group 0;");     \
            __syncthreads();                                                 \
            if (i + 2 < (total)) {                                           \
                int b2_ = (i + 2) % 3;                                       \
                ISSUE(i + 2, b2_);                                           \
            }                                                                \
            asm volatile("cp.async.commit_group;");                          \
            { int b_ = i % 3; MMA(i, b_); }                                  \
        }                                                                    \
        __syncthreads();                                                     \
    }

// ---------------- plain 2-term GEMM (for ii2) ----------------
__global__ void __launch_bounds__(256, 2) k_gemm2(
    const __half* __restrict__ A0, const __half* __restrict__ W0, int ldw0,
    const __half* __restrict__ A1, const __half* __restrict__ W1, int ldw1,
    const float* __restrict__ bias, __half* __restrict__ C, int N)
{
    extern __shared__ __align__(16) __half dynh[];
    __half* Abuf[3] = { dynh, dynh + 128 * STH, dynh + 2 * 128 * STH };
    __half* Wbuf[3] = { dynh + 3 * 128 * STH, dynh + 4 * 128 * STH, dynh + 5 * 128 * STH };
    const int tid = threadIdx.x, warp = tid >> 5, lane = tid & 31;
    const int row0 = blockIdx.x * 128, wm = warp >> 2, wn = warp & 3;

    FragAccH acc[4][2];
    acc_zero(acc);
    #define IS1(c, b) do { int kg = (c) * BK;                                          \
        const __half* A_ = (kg < 128) ? A0 : A1;                                        \
        const __half* W_ = (kg < 128) ? W0 : W1;                                        \
        int ld_ = (kg < 128) ? ldw0 : ldw1;                                             \
        cp_chunk(Abuf[b], Wbuf[b], A_, W_, ld_, kg & 127, row0, N, tid); } while (0)
    #define MM1(c, b) mma_step(acc, Abuf[b], STH, Wbuf[b], wm, wn)
    PIPE3(8, IS1, MM1)
    #undef IS1
    #undef MM1
    epi<0>(acc, (float*)dynh, bias, C, nullptr, nullptr, row0, N, warp, lane, wm, wn);
}

// ---------------- fused chain A: t0 = relu(e@ekS + n1@ekN + ekb) -> T + gmem;
//                  src = T@G1 + n1@G2 + e@w1b + gb -> gmem ----------------
__global__ void __launch_bounds__(256, 2) k_fusedA(
    const __half* __restrict__ eh, const __half* __restrict__ ekS,
    const __half* __restrict__ n1, const __half* __restrict__ ekN,
    const float* __restrict__ ekb,
    const __half* __restrict__ G1, const __half* __restrict__ G2,
    const __half* __restrict__ w1b, int ldw1b, const float* __restrict__ gb,
    __half* __restrict__ t0g, __half* __restrict__ srcg, int N)
{
    extern __shared__ __align__(16) __half dynh[];
    __half* Abuf[3] = { dynh, dynh + 128 * STH, dynh + 2 * 128 * STH };
    __half* Wbuf[3] = { dynh + 3 * 128 * STH, dynh + 4 * 128 * STH, dynh + 5 * 128 * STH };
    __half* Tt = dynh + 6 * 128 * STH;
    const int tid = threadIdx.x, warp = tid >> 5, lane = tid & 31;
    const int row0 = blockIdx.x * 128, wm = warp >> 2, wn = warp & 3;

    FragAccH acc[4][2];
    // ---- stage 1: t0 ----
    acc_zero(acc);
    #define ISA1(c, b) do { int kg = (c) * BK;                                         \
        const __half* A_ = (kg < 128) ? eh : n1;                                        \
        const __half* W_ = (kg < 128) ? ekS : ekN;                                      \
        cp_chunk(Abuf[b], Wbuf[b], A_, W_, DIM, kg & 127, row0, N, tid); } while (0)
    #define MMA1(c, b) mma_step(acc, Abuf[b], STH, Wbuf[b], wm, wn)
    PIPE3(8, ISA1, MMA1)
    #undef ISA1
    #undef MMA1
    epi<1>(acc, (float*)dynh, ekb, t0g, Tt, nullptr, row0, N, warp, lane, wm, wn);
    __syncthreads();

    // ---- stage 2: src = T@G1 + n1@G2 + e@w1b + gb ----
    acc_zero(acc);
    #define ISA2(c, b) do { int term_ = (c) >> 2, kl_ = ((c) & 3) * BK;                \
        if (term_ == 0)      cp_w(Wbuf[b], G1, DIM, kl_, tid);                          \
        else if (term_ == 1) cp_chunk(Abuf[b], Wbuf[b], n1, G2, DIM, kl_, row0, N, tid);\
        else                 cp_chunk(Abuf[b], Wbuf[b], eh, w1b, ldw1b, kl_, row0, N, tid); } while (0)
    #define MMA2(c, b) do { int term_ = (c) >> 2;                                      \
        if (term_ == 0) mma_step(acc, Tt + ((c) & 3) * BK, T_ST, Wbuf[b], wm, wn);      \
        else            mma_step(acc, Abuf[b], STH, Wbuf[b], wm, wn); } while (0)
    PIPE3(12, ISA2, MMA2)
    #undef ISA2
    #undef MMA2
    epi<0>(acc, (float*)dynh, gb, srcg, nullptr, nullptr, row0, N, warp, lane, wm, wn);
}

// ---------------- fused chain B: t1 = relu(e@eeS + n2@eeN + eeb) -> T only;
//                  out = T@F1 + t0@X1 + n1@X2 + n2@F2 + bout (leaky) -> float ----------------
__global__ void __launch_bounds__(256, 2) k_fusedB(
    const __half* __restrict__ eh, const __half* __restrict__ eeS,
    const __half* __restrict__ n2, const __half* __restrict__ eeN,
    const float* __restrict__ eeb,
    const __half* __restrict__ F1, const __half* __restrict__ t0g,
    const __half* __restrict__ X1, const __half* __restrict__ n1,
    const __half* __restrict__ X2, const __half* __restrict__ F2,
    const float* __restrict__ bout, float* __restrict__ outf, int N)
{
    extern __shared__ __align__(16) __half dynh[];
    __half* Abuf[3] = { dynh, dynh + 128 * STH, dynh + 2 * 128 * STH };
    __half* Wbuf[3] = { dynh + 3 * 128 * STH, dynh + 4 * 128 * STH, dynh + 5 * 128 * STH };
    __half* Tt = dynh + 6 * 128 * STH;
    const int tid = threadIdx.x, warp = tid >> 5, lane = tid & 31;
    const int row0 = blockIdx.x * 128, wm = warp >> 2, wn = warp & 3;

    FragAccH acc[4][2];
    // ---- stage 1: t1 -> T only ----
    acc_zero(acc);
    #define ISB1(c, b) do { int kg = (c) * BK;                                         \
        const __half* A_ = (kg < 128) ? eh : n2;                                        \
        const __half* W_ = (kg < 128) ? eeS : eeN;                                      \
        cp_chunk(Abuf[b], Wbuf[b], A_, W_, DIM, kg & 127, row0, N, tid); } while (0)
    #define MMB1(c, b) mma_step(acc, Abuf[b], STH, Wbuf[b], wm, wn)
    PIPE3(8, ISB1, MMB1)
    #undef ISB1
    #undef MMB1
    epi<1>(acc, (float*)dynh, eeb, nullptr, Tt, nullptr, row0, N, warp, lane, wm, wn);
    __syncthreads();

    // ---- stage 2: out = T@F1 + t0@X1 + n1@X2 + n2@F2 + bout ----
    acc_zero(acc);
    #define ISB2(c, b) do { int term_ = (c) >> 2, kl_ = ((c) & 3) * BK;                \
        if (term_ == 0)      cp_w(Wbuf[b], F1, DIM, kl_, tid);                          \
        else if (term_ == 1) cp_chunk(Abuf[b], Wbuf[b], t0g, X1, DIM, kl_, row0, N, tid);\
        else if (term_ == 2) cp_chunk(Abuf[b], Wbuf[b], n1, X2, DIM, kl_, row0, N, tid);\
        else                 cp_chunk(Abuf[b], Wbuf[b], n2, F2, DIM, kl_, row0, N, tid); } while (0)
    #define MMB2(c, b) do { int term_ = (c) >> 2;                                      \
        if (term_ == 0) mma_step(acc, Tt + ((c) & 3) * BK, T_ST, Wbuf[b], wm, wn);      \
        else            mma_step(acc, Abuf[b], STH, Wbuf[b], wm, wn); } while (0)
    PIPE3(16, ISB2, MMB2)
    #undef ISB2
    #undef MMB2
    epi<2>(acc, (float*)dynh, bout, nullptr, nullptr, outf, row0, N, warp, lane, wm, wn);
}

// ---------------- driver ----------------
extern "C" void kernel_launch(void* const* d_in, const int* in_sizes, int n_in,
                              void* d_out, int out_size)
{
    const float* ii    = (const float*)d_in[0];
    const float* e_emb = (const float*)d_in[1];
    const float* kemb  = (const float*)d_in[2];
    const float* cf_ew = (const float*)d_in[3];
    const int*   b_src = (const int*)d_in[4];
    const int*   b_dst = (const int*)d_in[5];
    const int*   c_src = (const int*)d_in[6];
    const int*   c_dst = (const int*)d_in[7];
    const float* ekS = (const float*)d_in[8];
    const float* ekN = (const float*)d_in[9];
    const float* ekb = (const float*)d_in[10];
    const float* eeS = (const float*)d_in[11];
    const float* eeN = (const float*)d_in[12];
    const float* eeb = (const float*)d_in[13];
    const float* w1W = (const float*)d_in[14];
    const float* w1b = (const float*)d_in[15];
    const float* w2W = (const float*)d_in[16];
    const float* w2b = (const float*)d_in[17];
    const float* w3W = (const float*)d_in[18];
    const float* w3b = (const float*)d_in[19];
    const float* w4W = (const float*)d_in[20];
    const float* w4b = (const float*)d_in[21];
    const float* cW  = (const float*)d_in[22];
    const float* cb  = (const float*)d_in[23];
    float* out = (float*)d_out;

    const int n_k = in_sizes[0] / DIM;
    const int n_e = in_sizes[1] / DIM;
    const int Eb  = in_sizes[4];
    const int Ec  = in_sizes[6];

    __half *eh, *ii2, *iih, *keh, *n1, *n2, *t0, *srcc;
    __half *w4h, *w1h, *ekSh, *ekNh, *eeSh, *eeNh, *G1, *G2, *X1, *X2, *F1, *F2;
    float *M2s, *M2n, *P, *b2, *bfv, *gb, *bout;
    int *cntB, *rowB, *curB, *choffB, *esrcB;
    int *cntC, *rowC, *curC, *choffC;
    int2 *epkC;
    cudaGetSymbolAddress((void**)&eh,    g_eh);
    cudaGetSymbolAddress((void**)&ii2,   g_ii2);
    cudaGetSymbolAddress((void**)&iih,   g_iih);
    cudaGetSymbolAddress((void**)&keh,   g_keh);
    cudaGetSymbolAddress((void**)&n1,    g_n1);
    cudaGetSymbolAddress((void**)&n2,    g_n2);
    cudaGetSymbolAddress((void**)&t0,    g_t0);
    cudaGetSymbolAddress((void**)&srcc,  g_srcc);
    cudaGetSymbolAddress((void**)&w4h,   g_w4h);
    cudaGetSymbolAddress((void**)&w1h,   g_w1h);
    cudaGetSymbolAddress((void**)&ekSh,  g_ekSh);
    cudaGetSymbolAddress((void**)&ekNh,  g_ekNh);
    cudaGetSymbolAddress((void**)&eeSh,  g_eeSh);
    cudaGetSymbolAddress((void**)&eeNh,  g_eeNh);
    cudaGetSymbolAddress((void**)&G1,    g_G1);
    cudaGetSymbolAddress((void**)&G2,    g_G2);
    cudaGetSymbolAddress((void**)&X1,    g_X1);
    cudaGetSymbolAddress((void**)&X2,    g_X2);
    cudaGetSymbolAddress((void**)&F1,    g_F1);
    cudaGetSymbolAddress((void**)&F2,    g_F2);
    cudaGetSymbolAddress((void**)&M2s,   g_M2s);
    cudaGetSymbolAddress((void**)&M2n,   g_M2n);
    cudaGetSymbolAddress((void**)&P,     g_P);
    cudaGetSymbolAddress((void**)&b2,    g_b2);
    cudaGetSymbolAddress((void**)&bfv,   g_bf);
    cudaGetSymbolAddress((void**)&gb,    g_gb);
    cudaGetSymbolAddress((void**)&bout,  g_bout);
    cudaGetSymbolAddress((void**)&cntB,  g_cntB);
    cudaGetSymbolAddress((void**)&rowB,  g_rowB);
    cudaGetSymbolAddress((void**)&curB,  g_curB);
    cudaGetSymbolAddress((void**)&choffB,g_choffB);
    cudaGetSymbolAddress((void**)&esrcB, g_esrcB);
    cudaGetSymbolAddress((void**)&cntC,  g_cntC);
    cudaGetSymbolAddress((void**)&rowC,  g_rowC);
    cudaGetSymbolAddress((void**)&curC,  g_curC);
    cudaGetSymbolAddress((void**)&choffC,g_choffC);
    cudaGetSymbolAddress((void**)&epkC,  g_epkC);

    static cudaStream_t sB = nullptr, sC = nullptr;
    static cudaEvent_t ev0 = nullptr, evB = nullptr, evCombo = nullptr, evC = nullptr;
    static bool init_done = false;
    if (!init_done) {
        cudaFuncSetAttribute(k_gemm2,  cudaFuncAttributeMaxDynamicSharedMemorySize, GEMM_SMEM);
        cudaFuncSetAttribute(k_fusedA, cudaFuncAttributeMaxDynamicSharedMemorySize, FUSED_SMEM);
        cudaFuncSetAttribute(k_fusedB, cudaFuncAttributeMaxDynamicSharedMemorySize, FUSED_SMEM);
        cudaStreamCreateWithFlags(&sB, cudaStreamNonBlocking);
        cudaStreamCreateWithFlags(&sC, cudaStreamNonBlocking);
        cudaEventCreateWithFlags(&ev0,     cudaEventDisableTiming);
        cudaEventCreateWithFlags(&evB,     cudaEventDisableTiming);
        cudaEventCreateWithFlags(&evCombo, cudaEventDisableTiming);
        cudaEventCreateWithFlags(&evC,     cudaEventDisableTiming);
        init_done = true;
    }

    const int gNe = (n_e + 127) / 128;
    const int gNk = (n_k + 127) / 128;
    const int gRows = (n_e * 32 + 255) / 256;
    const int nchunks = (n_e + SCAN_CHUNK - 1) / SCAN_CHUNK;

    // ---- fork ----
    cudaEventRecord(ev0, 0);
    cudaStreamWaitEvent(sB, ev0, 0);
    cudaStreamWaitEvent(sC, ev0, 0);

    // ---- stream B: belong CSR ----
    cudaMemsetAsync(cntB, 0, n_e * sizeof(int), sB);
    k_hist<<<(Eb + 255) / 256, 256, 0, sB>>>(b_dst, cntB, Eb);
    k_scan1<<<nchunks, 256, 0, sB>>>(cntB, rowB, choffB + 128, n_e);
    k_scan2<<<1, 256, 0, sB>>>(choffB + 128, choffB, nchunks);
    k_scan3<<<(n_e + 255) / 256, 256, 0, sB>>>(rowB, curB, choffB, n_e);
    k_scatter<<<(Eb + 255) / 256, 256, 0, sB>>>(b_src, b_dst, curB, esrcB, Eb);
    cudaEventRecord(evB, sB);

    // ---- stream C: conversions + folds + collab CSR ----
    k_f2h<<<(n_e * DIM / 4 + 255) / 256, 256, 0, sC>>>(eh, e_emb, n_e * DIM / 4);
    k_f2h<<<(DIM * DIM / 4 + 255) / 256, 256, 0, sC>>>(ekSh, ekS, DIM * DIM / 4);
    k_f2h<<<(DIM * DIM / 4 + 255) / 256, 256, 0, sC>>>(ekNh, ekN, DIM * DIM / 4);
    k_f2h<<<(DIM * DIM / 4 + 255) / 256, 256, 0, sC>>>(eeSh, eeS, DIM * DIM / 4);
    k_f2h<<<(DIM * DIM / 4 + 255) / 256, 256, 0, sC>>>(eeNh, eeN, DIM * DIM / 4);
    k_f2h<<<(2 * DIM * DIM / 4 + 255) / 256, 256, 0, sC>>>(w1h, w1W, 2 * DIM * DIM / 4);
    k_combo1<<<DIM, DIM, 0, sC>>>(w2W, w2b, ekS, ekN, ekb, cW, w3W, M2s, M2n, b2, P);
    k_combo2<<<DIM, DIM, 0, sC>>>(P, eeS, eeN, eeb, cW, w3b, cb, F1, F2, bfv);
    k_combo3<<<DIM, DIM, 0, sC>>>(w1W, w1b, cW, M2s, M2n, b2, bfv,
                                  G1, G2, X1, X2, gb, bout);
    cudaEventRecord(evCombo, sC);
    cudaMemsetAsync(cntC, 0, n_e * sizeof(int), sC);
    k_hist<<<(Ec + 255) / 256, 256, 0, sC>>>(c_dst, cntC, Ec);
    k_scan1<<<nchunks, 256, 0, sC>>>(cntC, rowC, choffC + 128, n_e);
    k_scan2<<<1, 256, 0, sC>>>(choffC + 128, choffC, nchunks);
    k_scan3<<<(n_e + 255) / 256, 256, 0, sC>>>(rowC, curC, choffC, n_e);
    k_scatter_p<<<(Ec + 255) / 256, 256, 0, sC>>>(c_src, c_dst, cf_ew, curC, epkC, Ec);
    cudaEventRecord(evC, sC);

    // ---- main stream ----
    k_f2h<<<(n_k * DIM / 4 + 255) / 256, 256>>>(iih, ii, n_k * DIM / 4);
    k_f2h<<<(n_k * DIM / 4 + 255) / 256, 256>>>(keh, kemb, n_k * DIM / 4);
    k_f2h<<<(2 * DIM * DIM / 4 + 255) / 256, 256>>>(w4h, w4W, 2 * DIM * DIM / 4);
    k_gemm2<<<gNk, 256, GEMM_SMEM>>>(iih, w4h, 2 * DIM, keh, w4h + DIM, 2 * DIM,
                                     w4b, ii2, n_k);
    cudaStreamWaitEvent(0, evB, 0);
    k_agg<<<gRows, 256>>>(ii2, rowB, cntB, esrcB, n1, n_e);

    // fused chain A: t0 (+gmem) then src
    cudaStreamWaitEvent(0, evCombo, 0);
    k_fusedA<<<gNe, 256, FUSED_SMEM>>>(eh, ekSh, n1, ekNh, ekb,
                                       G1, G2, w1h + DIM, 2 * DIM, gb,
                                       t0, srcc, n_e);

    cudaStreamWaitEvent(0, evC, 0);
    k_agg_p<<<gRows, 256>>>(srcc, rowC, cntC, epkC, n2, n_e);

    // fused chain B: t1 (smem only) then out
    k_fusedB<<<gNe, 256, FUSED_SMEM>>>(eh, eeSh, n2, eeNh, eeb,
                                       F1, t0, X1, n1, X2, F2,
                                       bout, out, n_e);
}